// round 2
// baseline (speedup 1.0000x reference)
#include <cuda_runtime.h>
#include <cuda_bf16.h>
#include <math_constants.h>

#define HW 13
#define NTOK 169
#define BATCH 256

// ---- scratch (device globals; no allocation allowed) ----
__device__ float g_F[BATCH * 64 * NTOK];      // [b][c][n]
__device__ float g_G[BATCH * 64 * NTOK];      // [b][c][n]
__device__ float g_S[BATCH * NTOK * NTOK];    // [b][i][n]  (H + U + attention)
__device__ float g_pool[BATCH * 128 * NTOK];  // [b][c][n]  antialiased 26->13

// ============================================================
// Antialiased bilinear downsample 26 -> 13 (jax.image.resize default
// antialias=True): separable triangle filter, radius 2 at scale 0.5.
// Output i samples input at 2i+0.5 with taps [0.125,0.375,0.375,0.125]
// at rows {2i-1,2i,2i+1,2i+2}; boundary taps dropped and renormalized.
// ============================================================
__constant__ int   c_tap0[HW] = { 0, 1, 3, 5, 7, 9,11,13,15,17,19,21,23};
__constant__ float c_w[HW][4] = {
    {3.f/7.f, 3.f/7.f, 1.f/7.f, 0.f},              // i=0 (taps 0,1,2)
    {0.125f, 0.375f, 0.375f, 0.125f},               // i=1..11
    {0.125f, 0.375f, 0.375f, 0.125f},
    {0.125f, 0.375f, 0.375f, 0.125f},
    {0.125f, 0.375f, 0.375f, 0.125f},
    {0.125f, 0.375f, 0.375f, 0.125f},
    {0.125f, 0.375f, 0.375f, 0.125f},
    {0.125f, 0.375f, 0.375f, 0.125f},
    {0.125f, 0.375f, 0.375f, 0.125f},
    {0.125f, 0.375f, 0.375f, 0.125f},
    {0.125f, 0.375f, 0.375f, 0.125f},
    {0.125f, 0.375f, 0.375f, 0.125f},
    {1.f/7.f, 3.f/7.f, 3.f/7.f, 0.f}                // i=12 (taps 23,24,25)
};

__global__ __launch_bounds__(256) void pool_kernel(const float* __restrict__ f5) {
    int idx = blockIdx.x * blockDim.x + threadIdx.x;
    const int total = BATCH * 128 * NTOK;
    if (idx >= total) return;
    int n  = idx % NTOK;
    int bc = idx / NTOK;
    int j = n % HW, i = n / HW;
    const float* src = f5 + (size_t)bc * 26 * 26;

    int r0 = c_tap0[i], cc0 = c_tap0[j];
    float acc = 0.f;
#pragma unroll
    for (int ri = 0; ri < 4; ri++) {
        float wr = c_w[i][ri];
        if (wr == 0.f) continue;
        int r = r0 + ri;
        float rowv = 0.f;
#pragma unroll
        for (int ci = 0; ci < 4; ci++) {
            float wc = c_w[j][ci];
            if (wc == 0.f) continue;
            rowv = fmaf(wc, src[r * 26 + cc0 + ci], rowv);
        }
        acc = fmaf(wr, rowv, acc);
    }
    g_pool[idx] = acc;
}

// ============================================================
// Generic batched GEMM: C[b] (M x 169) = W (M x K) @ In[b] (K x 169) + bias
// MODE 0: Out = v
// MODE 1: Out += v
// MODE 2: Out = gamma * v + res   (final conv + residual)
// grid = (ceil(M/64), BATCH), block = 256
// ============================================================
template <int MODE>
__global__ __launch_bounds__(256) void gemm_kernel(
    const float* __restrict__ W, const float* __restrict__ bias,
    const float* __restrict__ In, float* __restrict__ Out,
    int M, int K,
    const float* __restrict__ res, const float* __restrict__ gamma_p)
{
    const int BM = 64, BK = 32;
    __shared__ float Ws[BK][BM + 1];   // [k][m], pad for conflict-free
    __shared__ float Xs[BK][176];      // [k][n], 176 >= 169 padded

    int b   = blockIdx.y;
    int m0  = blockIdx.x * BM;
    int tid = threadIdx.x;
    int tx  = tid & 15;    // column group (16)
    int ty  = tid >> 4;    // row group (16)

    const float* Inb = In + (size_t)b * K * NTOK;

    float acc[4][11];
#pragma unroll
    for (int r = 0; r < 4; r++)
#pragma unroll
        for (int j = 0; j < 11; j++) acc[r][j] = 0.f;

    for (int k0 = 0; k0 < K; k0 += BK) {
        // load W tile (coalesced over k), transposed into Ws[k][m]
#pragma unroll
        for (int idx = tid; idx < BM * BK; idx += 256) {
            int m = idx >> 5, kk = idx & 31;
            int gm = m0 + m, gk = k0 + kk;
            Ws[kk][m] = (gm < M && gk < K) ? W[(size_t)gm * K + gk] : 0.f;
        }
        // load In tile (coalesced over n)
        for (int idx = tid; idx < BK * NTOK; idx += 256) {
            int kk = idx / NTOK, n = idx - kk * NTOK;
            int gk = k0 + kk;
            Xs[kk][n] = (gk < K) ? Inb[(size_t)gk * NTOK + n] : 0.f;
        }
        __syncthreads();
#pragma unroll
        for (int kk = 0; kk < BK; kk++) {
            float rw[4], rx[11];
#pragma unroll
            for (int r = 0; r < 4; r++) rw[r] = Ws[kk][ty * 4 + r];
#pragma unroll
            for (int j = 0; j < 11; j++) rx[j] = Xs[kk][tx + 16 * j];
#pragma unroll
            for (int r = 0; r < 4; r++)
#pragma unroll
                for (int j = 0; j < 11; j++)
                    acc[r][j] = fmaf(rw[r], rx[j], acc[r][j]);
        }
        __syncthreads();
    }

    float gma = (MODE == 2) ? *gamma_p : 0.f;
    float* Outb = Out + (size_t)b * M * NTOK;
    const float* resb = (MODE == 2) ? res + (size_t)b * M * NTOK : nullptr;

#pragma unroll
    for (int r = 0; r < 4; r++) {
        int m = m0 + ty * 4 + r;
        if (m >= M) continue;
        float bv = bias[m];
#pragma unroll
        for (int j = 0; j < 11; j++) {
            int n = tx + 16 * j;
            if (n >= NTOK) continue;
            size_t o = (size_t)m * NTOK + n;
            float v = acc[r][j] + bv;
            if (MODE == 0)      Outb[o] = v;
            else if (MODE == 1) Outb[o] += v;
            else                Outb[o] = gma * v + resb[o];
        }
    }
}

// ============================================================
// energy + softmax + accumulate into S.
// E[n,m] = sum_c F[c][n] * G[c][m]; A = softmax over m; S[n,m] += A[n,m]
// grid = (3, BATCH)  (row tiles of 64), block = 256
// ============================================================
__global__ __launch_bounds__(256) void attn_kernel()
{
    __shared__ float Fs[32][68];    // [c][n_local]
    __shared__ float Gs[32][176];   // [c][m]

    int b   = blockIdx.y;
    int n0  = blockIdx.x * 64;
    int tid = threadIdx.x;
    int tx  = tid & 15;
    int ty  = tid >> 4;

    const float* Fb = g_F + (size_t)b * 64 * NTOK;
    const float* Gb = g_G + (size_t)b * 64 * NTOK;

    float acc[4][11];
#pragma unroll
    for (int r = 0; r < 4; r++)
#pragma unroll
        for (int j = 0; j < 11; j++) acc[r][j] = 0.f;

    for (int c0 = 0; c0 < 64; c0 += 32) {
        for (int idx = tid; idx < 32 * 64; idx += 256) {
            int c = idx >> 6, nl = idx & 63;
            int n = n0 + nl;
            Fs[c][nl] = (n < NTOK) ? Fb[(size_t)(c0 + c) * NTOK + n] : 0.f;
        }
        for (int idx = tid; idx < 32 * NTOK; idx += 256) {
            int c = idx / NTOK, m = idx - c * NTOK;
            Gs[c][m] = Gb[(size_t)(c0 + c) * NTOK + m];
        }
        __syncthreads();
#pragma unroll
        for (int c = 0; c < 32; c++) {
            float rf[4], rg[11];
#pragma unroll
            for (int r = 0; r < 4; r++) rf[r] = Fs[c][ty * 4 + r];
#pragma unroll
            for (int j = 0; j < 11; j++) rg[j] = Gs[c][tx + 16 * j];
#pragma unroll
            for (int r = 0; r < 4; r++)
#pragma unroll
                for (int j = 0; j < 11; j++)
                    acc[r][j] = fmaf(rf[r], rg[j], acc[r][j]);
        }
        __syncthreads();
    }

    // softmax per row; row n = n0 + ty*4 + r is owned by the 16 lanes sharing ty
    float* Sb = g_S + (size_t)b * NTOK * NTOK;
#pragma unroll
    for (int r = 0; r < 4; r++) {
        int n = n0 + ty * 4 + r;
        float mx = -CUDART_INF_F;
#pragma unroll
        for (int j = 0; j < 11; j++) {
            int m = tx + 16 * j;
            if (m < NTOK) mx = fmaxf(mx, acc[r][j]);
        }
#pragma unroll
        for (int off = 8; off > 0; off >>= 1)
            mx = fmaxf(mx, __shfl_xor_sync(0xffffffffu, mx, off, 16));

        float e[11];
        float sum = 0.f;
#pragma unroll
        for (int j = 0; j < 11; j++) {
            int m = tx + 16 * j;
            e[j] = (m < NTOK) ? __expf(acc[r][j] - mx) : 0.f;
            sum += e[j];
        }
#pragma unroll
        for (int off = 8; off > 0; off >>= 1)
            sum += __shfl_xor_sync(0xffffffffu, sum, off, 16);

        float inv = 1.f / sum;
        if (n < NTOK) {
#pragma unroll
            for (int j = 0; j < 11; j++) {
                int m = tx + 16 * j;
                if (m < NTOK) {
                    size_t o = (size_t)n * NTOK + m;
                    Sb[o] += e[j] * inv;
                }
            }
        }
    }
}

// ============================================================
extern "C" void kernel_launch(void* const* d_in, const int* in_sizes, int n_in,
                              void* d_out, int out_size)
{
    const float* x    = (const float*)d_in[0];   // [256,512,169]
    const float* f5   = (const float*)d_in[1];   // [256,128,26,26]
    const float* f8   = (const float*)d_in[2];   // [256,256,169]
    const float* f_w  = (const float*)d_in[3];   // [64,512]
    const float* f_b  = (const float*)d_in[4];
    const float* g_w  = (const float*)d_in[5];
    const float* g_b  = (const float*)d_in[6];
    const float* h_w  = (const float*)d_in[7];   // [169,256]
    const float* h_b  = (const float*)d_in[8];
    const float* u_w  = (const float*)d_in[9];   // [169,128]
    const float* u_b  = (const float*)d_in[10];
    const float* c_w  = (const float*)d_in[11];  // [512,169]
    const float* c_b  = (const float*)d_in[12];
    const float* gma  = (const float*)d_in[13];  // scalar

    float* out = (float*)d_out;

    float* Fp; cudaGetSymbolAddress((void**)&Fp, g_F);
    float* Gp; cudaGetSymbolAddress((void**)&Gp, g_G);
    float* Sp; cudaGetSymbolAddress((void**)&Sp, g_S);
    float* Pp; cudaGetSymbolAddress((void**)&Pp, g_pool);

    // 1) antialiased downsample of f5 (26x26 -> 13x13)
    {
        int total = BATCH * 128 * NTOK;
        pool_kernel<<<(total + 255) / 256, 256>>>(f5);
    }
    // 2) F = f_w @ x + f_b ; G = g_w @ x + g_b
    gemm_kernel<0><<<dim3(1, BATCH), 256>>>(f_w, f_b, x, Fp, 64, 512, nullptr, nullptr);
    gemm_kernel<0><<<dim3(1, BATCH), 256>>>(g_w, g_b, x, Gp, 64, 512, nullptr, nullptr);
    // 3) S = h_w @ f8 + h_b
    gemm_kernel<0><<<dim3(3, BATCH), 256>>>(h_w, h_b, f8, Sp, NTOK, 256, nullptr, nullptr);
    // 4) S += u_w @ pool + u_b
    gemm_kernel<1><<<dim3(3, BATCH), 256>>>(u_w, u_b, Pp, Sp, NTOK, 128, nullptr, nullptr);
    // 5) S += softmax(F^T G)
    attn_kernel<<<dim3(3, BATCH), 256>>>();
    // 6) out = gamma * (c_w @ S + c_b) + x
    gemm_kernel<2><<<dim3(8, BATCH), 256>>>(c_w, c_b, Sp, out, 512, NTOK, x, gma);
}

// round 3
// speedup vs baseline: 1.0583x; 1.0583x over previous
#include <cuda_runtime.h>
#include <cuda_bf16.h>
#include <math_constants.h>

#define HW 13
#define NTOK 169
#define BATCH 256

typedef unsigned long long ull;

// ---- scratch (device globals; no allocation allowed) ----
__device__ float g_F[BATCH * 64 * NTOK];      // [b][c][n]
__device__ float g_G[BATCH * 64 * NTOK];      // [b][c][n]
__device__ float g_S[BATCH * NTOK * NTOK];    // [b][row][col]
__device__ float g_pool[BATCH * 128 * NTOK];  // [b][c][n]

// ============================================================
// packed fp32x2 helpers
// ============================================================
__device__ __forceinline__ void fma2(ull& d, ull a, ull b) {
    asm("fma.rn.f32x2 %0, %1, %2, %0;" : "+l"(d) : "l"(a), "l"(b));
}
__device__ __forceinline__ ull pack2(float x, float y) {
    ull r; asm("mov.b64 %0, {%1,%2};" : "=l"(r) : "f"(x), "f"(y)); return r;
}
__device__ __forceinline__ float2 unpack2(ull v) {
    float2 f; asm("mov.b64 {%0,%1}, %2;" : "=f"(f.x), "=f"(f.y) : "l"(v)); return f;
}

// ============================================================
// shared tile: Ws[k][m] scalar (padded), Xs[k][n] padded to 192 cols
// ============================================================
struct Tile {
    float Ws[32][65];
    float Xs[32][192];
};

// W [M][K] row-major -> Ws[kk][m] (transposed), zero-guarded
__device__ __forceinline__ void fill_W(Tile& t, const float* __restrict__ W,
                                       int m0, int k0, int M, int K, int tid) {
#pragma unroll
    for (int idx = tid; idx < 64 * 32; idx += 256) {
        int m = idx >> 5, kk = idx & 31;
        int gm = m0 + m, gk = k0 + kk;
        t.Ws[kk][m] = (gm < M && gk < K) ? W[(size_t)gm * K + gk] : 0.f;
    }
}
// c-major source Wc [C][NTOK] -> Ws[kk][m] = Wc[k0+kk][n0+m]
__device__ __forceinline__ void fill_Wc(Tile& t, const float* __restrict__ Wc,
                                        int n0, int k0, int tid) {
#pragma unroll
    for (int idx = tid; idx < 32 * 64; idx += 256) {
        int kk = idx >> 6, m = idx & 63;
        int n = n0 + m;
        t.Ws[kk][m] = (n < NTOK) ? Wc[(size_t)(k0 + kk) * NTOK + n] : 0.f;
    }
}
// In [K][NTOK] -> Xs[kk][n], zero-pad to 192 cols
__device__ __forceinline__ void fill_X(Tile& t, const float* __restrict__ In,
                                       int k0, int K, int tid) {
#pragma unroll
    for (int idx = tid; idx < 32 * 192; idx += 256) {
        int kk = idx / 192, n = idx - kk * 192;
        int gk = k0 + kk;
        t.Xs[kk][n] = (gk < K && n < NTOK) ? In[(size_t)gk * NTOK + n] : 0.f;
    }
}

// main accumulate: 4 rows x 6 col-pairs per thread, BK=32
__device__ __forceinline__ void mma_tile(ull (&acc)[4][6], const Tile& t, int tx, int ty) {
#pragma unroll
    for (int kk = 0; kk < 32; kk++) {
        ull x[6];
#pragma unroll
        for (int jp = 0; jp < 6; jp++)
            x[jp] = *(const ull*)&t.Xs[kk][2 * tx + 32 * jp];
        ull w[4];
#pragma unroll
        for (int r = 0; r < 4; r++) {
            float ws = t.Ws[kk][ty * 4 + r];
            w[r] = pack2(ws, ws);
        }
#pragma unroll
        for (int r = 0; r < 4; r++)
#pragma unroll
            for (int jp = 0; jp < 6; jp++)
                fma2(acc[r][jp], w[r], x[jp]);
    }
}

// ============================================================
// Antialiased bilinear downsample 26 -> 13 (jax default antialias=True)
// ============================================================
__constant__ int   c_tap0[HW] = { 0, 1, 3, 5, 7, 9,11,13,15,17,19,21,23};
__constant__ float c_wt[HW][4] = {
    {3.f/7.f, 3.f/7.f, 1.f/7.f, 0.f},
    {0.125f, 0.375f, 0.375f, 0.125f}, {0.125f, 0.375f, 0.375f, 0.125f},
    {0.125f, 0.375f, 0.375f, 0.125f}, {0.125f, 0.375f, 0.375f, 0.125f},
    {0.125f, 0.375f, 0.375f, 0.125f}, {0.125f, 0.375f, 0.375f, 0.125f},
    {0.125f, 0.375f, 0.375f, 0.125f}, {0.125f, 0.375f, 0.375f, 0.125f},
    {0.125f, 0.375f, 0.375f, 0.125f}, {0.125f, 0.375f, 0.375f, 0.125f},
    {0.125f, 0.375f, 0.375f, 0.125f},
    {1.f/7.f, 3.f/7.f, 3.f/7.f, 0.f}
};

__global__ __launch_bounds__(256) void pool_kernel(const float* __restrict__ f5) {
    int idx = blockIdx.x * blockDim.x + threadIdx.x;
    const int total = BATCH * 128 * NTOK;
    if (idx >= total) return;
    int n  = idx % NTOK;
    int bc = idx / NTOK;
    int j = n % HW, i = n / HW;
    const float* src = f5 + (size_t)bc * 26 * 26;
    int r0 = c_tap0[i], cc0 = c_tap0[j];
    float acc = 0.f;
#pragma unroll
    for (int ri = 0; ri < 4; ri++) {
        float wr = c_wt[i][ri];
        if (wr == 0.f) continue;
        int r = r0 + ri;
        float rowv = 0.f;
#pragma unroll
        for (int ci = 0; ci < 4; ci++) {
            float wc = c_wt[j][ci];
            if (wc == 0.f) continue;
            rowv = fmaf(wc, src[r * 26 + cc0 + ci], rowv);
        }
        acc = fmaf(wr, rowv, acc);
    }
    g_pool[idx] = acc;
}

// ============================================================
// F and G projections: grid (2, BATCH); blockIdx.x selects f/g
// ============================================================
__global__ __launch_bounds__(256) void fg_kernel(
    const float* __restrict__ x,
    const float* __restrict__ f_w, const float* __restrict__ f_b,
    const float* __restrict__ g_w, const float* __restrict__ g_b)
{
    __shared__ Tile t;
    int b   = blockIdx.y;
    int tid = threadIdx.x;
    int tx  = tid & 15, ty = tid >> 4;

    const float* W    = blockIdx.x ? g_w : f_w;
    const float* bias = blockIdx.x ? g_b : f_b;
    float* Out = (blockIdx.x ? g_G : g_F) + (size_t)b * 64 * NTOK;
    const float* In = x + (size_t)b * 512 * NTOK;

    ull acc[4][6] = {};
    for (int k0 = 0; k0 < 512; k0 += 32) {
        fill_W(t, W, 0, k0, 64, 512, tid);
        fill_X(t, In, k0, 512, tid);
        __syncthreads();
        mma_tile(acc, t, tx, ty);
        __syncthreads();
    }
#pragma unroll
    for (int r = 0; r < 4; r++) {
        int m = ty * 4 + r;
        float bv = bias[m];
        float* orow = Out + (size_t)m * NTOK;
#pragma unroll
        for (int jp = 0; jp < 6; jp++) {
            int col = 2 * tx + 32 * jp;
            float2 v = unpack2(acc[r][jp]);
            if (col     < NTOK) orow[col]     = v.x + bv;
            if (col + 1 < NTOK) orow[col + 1] = v.y + bv;
        }
    }
}

// ============================================================
// S = softmax(F^T G) + h_w@f8 + u_w@pool + (h_b+u_b)
// grid (3, BATCH); one acc set: energy -> softmax in place -> keep accumulating
// ============================================================
__global__ __launch_bounds__(256) void s_kernel(
    const float* __restrict__ f8,
    const float* __restrict__ h_w, const float* __restrict__ h_b,
    const float* __restrict__ u_w, const float* __restrict__ u_b)
{
    __shared__ Tile t;
    int b   = blockIdx.y;
    int n0  = blockIdx.x * 64;
    int tid = threadIdx.x;
    int tx  = tid & 15, ty = tid >> 4;

    const float* Fb = g_F + (size_t)b * 64 * NTOK;
    const float* Gb = g_G + (size_t)b * 64 * NTOK;

    ull acc[4][6] = {};

    // ---- energy = F^T G over K=64 ----
    for (int k0 = 0; k0 < 64; k0 += 32) {
        fill_Wc(t, Fb, n0, k0, tid);
        fill_X(t, Gb, k0, 64, tid);
        __syncthreads();
        mma_tile(acc, t, tx, ty);
        __syncthreads();
    }

    // ---- softmax in place over cols (16 lanes per row, shfl width 16) ----
#pragma unroll
    for (int r = 0; r < 4; r++) {
        float v[12];
#pragma unroll
        for (int jp = 0; jp < 6; jp++) {
            float2 f = unpack2(acc[r][jp]);
            v[2 * jp] = f.x; v[2 * jp + 1] = f.y;
        }
        float mx = -CUDART_INF_F;
#pragma unroll
        for (int j = 0; j < 12; j++) {
            int col = 2 * tx + 32 * (j >> 1) + (j & 1);
            if (col < NTOK) mx = fmaxf(mx, v[j]);
        }
#pragma unroll
        for (int off = 8; off > 0; off >>= 1)
            mx = fmaxf(mx, __shfl_xor_sync(0xffffffffu, mx, off, 16));
        float sum = 0.f;
#pragma unroll
        for (int j = 0; j < 12; j++) {
            int col = 2 * tx + 32 * (j >> 1) + (j & 1);
            float e = (col < NTOK) ? __expf(v[j] - mx) : 0.f;
            v[j] = e; sum += e;
        }
#pragma unroll
        for (int off = 8; off > 0; off >>= 1)
            sum += __shfl_xor_sync(0xffffffffu, sum, off, 16);
        float inv = 1.f / sum;
#pragma unroll
        for (int jp = 0; jp < 6; jp++)
            acc[r][jp] = pack2(v[2 * jp] * inv, v[2 * jp + 1] * inv);
    }

    // ---- += h_w @ f8 (K=256) ----
    const float* f8b = f8 + (size_t)b * 256 * NTOK;
    for (int k0 = 0; k0 < 256; k0 += 32) {
        fill_W(t, h_w, n0, k0, NTOK, 256, tid);
        fill_X(t, f8b, k0, 256, tid);
        __syncthreads();
        mma_tile(acc, t, tx, ty);
        __syncthreads();
    }
    // ---- += u_w @ pool (K=128) ----
    const float* plb = g_pool + (size_t)b * 128 * NTOK;
    for (int k0 = 0; k0 < 128; k0 += 32) {
        fill_W(t, u_w, n0, k0, NTOK, 128, tid);
        fill_X(t, plb, k0, 128, tid);
        __syncthreads();
        mma_tile(acc, t, tx, ty);
        __syncthreads();
    }

    // ---- write S ----
    float* Sb = g_S + (size_t)b * NTOK * NTOK;
#pragma unroll
    for (int r = 0; r < 4; r++) {
        int n = n0 + ty * 4 + r;
        if (n >= NTOK) continue;
        float bv = h_b[n] + u_b[n];
        float* srow = Sb + (size_t)n * NTOK;
#pragma unroll
        for (int jp = 0; jp < 6; jp++) {
            int col = 2 * tx + 32 * jp;
            float2 v = unpack2(acc[r][jp]);
            if (col     < NTOK) srow[col]     = v.x + bv;
            if (col + 1 < NTOK) srow[col + 1] = v.y + bv;
        }
    }
}

// ============================================================
// out = gamma * (c_w @ S + c_b) + x     grid (8, BATCH)
// ============================================================
__global__ __launch_bounds__(256) void out_kernel(
    const float* __restrict__ c_w, const float* __restrict__ c_b,
    const float* __restrict__ x, const float* __restrict__ gamma_p,
    float* __restrict__ Out)
{
    __shared__ Tile t;
    int b   = blockIdx.y;
    int m0  = blockIdx.x * 64;
    int tid = threadIdx.x;
    int tx  = tid & 15, ty = tid >> 4;

    const float* Sb = g_S + (size_t)b * NTOK * NTOK;

    ull acc[4][6] = {};
    for (int k0 = 0; k0 < NTOK; k0 += 32) {
        fill_W(t, c_w, m0, k0, 512, NTOK, tid);
        fill_X(t, Sb, k0, NTOK, tid);
        __syncthreads();
        mma_tile(acc, t, tx, ty);
        __syncthreads();
    }

    float gma = *gamma_p;
    const float* xb = x + (size_t)b * 512 * NTOK;
    float* ob = Out + (size_t)b * 512 * NTOK;
#pragma unroll
    for (int r = 0; r < 4; r++) {
        int m = m0 + ty * 4 + r;
        float bv = c_b[m];
        const float* xrow = xb + (size_t)m * NTOK;
        float* orow = ob + (size_t)m * NTOK;
#pragma unroll
        for (int jp = 0; jp < 6; jp++) {
            int col = 2 * tx + 32 * jp;
            float2 v = unpack2(acc[r][jp]);
            if (col     < NTOK) orow[col]     = fmaf(gma, v.x + bv, xrow[col]);
            if (col + 1 < NTOK) orow[col + 1] = fmaf(gma, v.y + bv, xrow[col + 1]);
        }
    }
}

// ============================================================
extern "C" void kernel_launch(void* const* d_in, const int* in_sizes, int n_in,
                              void* d_out, int out_size)
{
    const float* x    = (const float*)d_in[0];
    const float* f5   = (const float*)d_in[1];
    const float* f8   = (const float*)d_in[2];
    const float* f_w  = (const float*)d_in[3];
    const float* f_b  = (const float*)d_in[4];
    const float* g_w  = (const float*)d_in[5];
    const float* g_b  = (const float*)d_in[6];
    const float* h_w  = (const float*)d_in[7];
    const float* h_b  = (const float*)d_in[8];
    const float* u_w  = (const float*)d_in[9];
    const float* u_b  = (const float*)d_in[10];
    const float* c_w  = (const float*)d_in[11];
    const float* c_b  = (const float*)d_in[12];
    const float* gma  = (const float*)d_in[13];

    float* out = (float*)d_out;

    {
        int total = BATCH * 128 * NTOK;
        pool_kernel<<<(total + 255) / 256, 256>>>(f5);
    }
    fg_kernel<<<dim3(2, BATCH), 256>>>(x, f_w, f_b, g_w, g_b);
    s_kernel<<<dim3(3, BATCH), 256>>>(f8, h_w, h_b, u_w, u_b);
    out_kernel<<<dim3(8, BATCH), 256>>>(c_w, c_b, x, gma, out);
}

// round 4
// speedup vs baseline: 1.3640x; 1.2889x over previous
#include <cuda_runtime.h>
#include <cuda_bf16.h>
#include <math_constants.h>

#define HW 13
#define NTOK 169
#define NP 176          // padded row stride for intermediates
#define BATCH 256

typedef unsigned long long ull;

// ---- scratch (device globals; padded to NP cols) ----
__device__ float g_F[BATCH * 64 * NP];
__device__ float g_G[BATCH * 64 * NP];
__device__ float g_S[BATCH * NTOK * NP];
__device__ float g_pool[BATCH * 128 * NP];

// ============================================================
// packed fp32x2 helpers
// ============================================================
__device__ __forceinline__ void fma2(ull& d, ull a, ull b) {
    asm("fma.rn.f32x2 %0, %1, %2, %0;" : "+l"(d) : "l"(a), "l"(b));
}
__device__ __forceinline__ ull pack2(float x, float y) {
    ull r; asm("mov.b64 %0, {%1,%2};" : "=l"(r) : "f"(x), "f"(y)); return r;
}
__device__ __forceinline__ float2 unpack2(ull v) {
    float2 f; asm("mov.b64 {%0,%1}, %2;" : "=f"(f.x), "=f"(f.y) : "l"(v)); return f;
}

// ============================================================
// cp.async 4B with zero-fill predicate
// ============================================================
__device__ __forceinline__ void cpa4(void* dst, const float* src, bool ok) {
    unsigned d = (unsigned)__cvta_generic_to_shared(dst);
    int sz = ok ? 4 : 0;
    asm volatile("cp.async.ca.shared.global [%0], [%1], 4, %2;" :: "r"(d), "l"(src), "r"(sz));
}
#define CP_COMMIT()  asm volatile("cp.async.commit_group;")
#define CP_WAIT1()   asm volatile("cp.async.wait_group 1;")
#define CP_WAIT0()   asm volatile("cp.async.wait_group 0;")

// ============================================================
// double-buffered tile (BK = 16)
// ============================================================
struct Buf {
    float Ws[16][65];    // [k][m]
    float Xs[16][192];   // [k][n]
};

// WMODE 0: W is row-major [M][K]  -> Ws[kk][m] = W[m0+m][k0+kk]
// WMODE 1: W is col-major [K][NP] -> Ws[kk][m] = W[k0+kk][m0+m]  (m0 = n0)
template <int WMODE>
__device__ __forceinline__ void fill_tile(Buf& b, const float* __restrict__ W,
                                          int m0, int M,
                                          const float* __restrict__ X, int ldx,
                                          int k0, int K, int tid)
{
    if (WMODE == 0) {
#pragma unroll
        for (int i = 0; i < 4; i++) {
            int idx = tid + i * 256;
            int m = idx >> 4, kk = idx & 15;
            int gm = m0 + m, gk = k0 + kk;
            bool ok = (gm < M) && (gk < K);
            cpa4(&b.Ws[kk][m], W + (size_t)gm * K + gk, ok);
        }
    } else {
#pragma unroll
        for (int i = 0; i < 4; i++) {
            int idx = tid + i * 256;
            int kk = idx >> 6, m = idx & 63;
            int n = m0 + m;
            bool ok = (n < NTOK) && (k0 + kk < K);
            cpa4(&b.Ws[kk][m], W + (size_t)(k0 + kk) * NP + n, ok);
        }
    }
#pragma unroll
    for (int i = 0; i < 12; i++) {
        int idx = tid + i * 256;
        int kk = idx / 192, n = idx - kk * 192;
        bool ok = (n < NTOK) && (k0 + kk < K);
        cpa4(&b.Xs[kk][n], X + (size_t)(k0 + kk) * ldx + n, ok);
    }
}

__device__ __forceinline__ void mma_tile(ull (&acc)[4][6], const Buf& b, int tx, int ty) {
#pragma unroll 4
    for (int kk = 0; kk < 16; kk++) {
        ull x[6];
#pragma unroll
        for (int jp = 0; jp < 6; jp++)
            x[jp] = *(const ull*)&b.Xs[kk][2 * tx + 32 * jp];
        ull w[4];
#pragma unroll
        for (int r = 0; r < 4; r++) {
            float ws = b.Ws[kk][ty * 4 + r];
            w[r] = pack2(ws, ws);
        }
#pragma unroll
        for (int r = 0; r < 4; r++)
#pragma unroll
            for (int jp = 0; jp < 6; jp++)
                fma2(acc[r][jp], w[r], x[jp]);
    }
}

template <int WMODE>
__device__ __forceinline__ void run_gemm(Buf* bufs, ull (&acc)[4][6],
                                         const float* __restrict__ W, int m0, int M,
                                         const float* __restrict__ X, int ldx, int K,
                                         int tid, int tx, int ty)
{
    int nt = (K + 15) >> 4;
    fill_tile<WMODE>(bufs[0], W, m0, M, X, ldx, 0, K, tid);
    CP_COMMIT();
    for (int t = 0; t < nt; t++) {
        if (t + 1 < nt) {
            fill_tile<WMODE>(bufs[(t + 1) & 1], W, m0, M, X, ldx, (t + 1) << 4, K, tid);
            CP_COMMIT();
            CP_WAIT1();
        } else {
            CP_WAIT0();
        }
        __syncthreads();
        mma_tile(acc, bufs[t & 1], tx, ty);
        __syncthreads();
    }
}

// ============================================================
// Antialiased bilinear downsample 26 -> 13 (jax antialias=True)
// ============================================================
__constant__ int   c_tap0[HW] = { 0, 1, 3, 5, 7, 9,11,13,15,17,19,21,23};
__constant__ float c_wt[HW][4] = {
    {3.f/7.f, 3.f/7.f, 1.f/7.f, 0.f},
    {0.125f, 0.375f, 0.375f, 0.125f}, {0.125f, 0.375f, 0.375f, 0.125f},
    {0.125f, 0.375f, 0.375f, 0.125f}, {0.125f, 0.375f, 0.375f, 0.125f},
    {0.125f, 0.375f, 0.375f, 0.125f}, {0.125f, 0.375f, 0.375f, 0.125f},
    {0.125f, 0.375f, 0.375f, 0.125f}, {0.125f, 0.375f, 0.375f, 0.125f},
    {0.125f, 0.375f, 0.375f, 0.125f}, {0.125f, 0.375f, 0.375f, 0.125f},
    {0.125f, 0.375f, 0.375f, 0.125f},
    {1.f/7.f, 3.f/7.f, 3.f/7.f, 0.f}
};

__global__ __launch_bounds__(256) void pool_kernel(const float* __restrict__ f5) {
    int idx = blockIdx.x * blockDim.x + threadIdx.x;
    const int total = BATCH * 128 * NTOK;
    if (idx >= total) return;
    int n  = idx % NTOK;
    int bc = idx / NTOK;
    int j = n % HW, i = n / HW;
    const float* src = f5 + (size_t)bc * 26 * 26;
    int r0 = c_tap0[i], cc0 = c_tap0[j];
    float acc = 0.f;
#pragma unroll
    for (int ri = 0; ri < 4; ri++) {
        float wr = c_wt[i][ri];
        if (wr == 0.f) continue;
        int r = r0 + ri;
        float rowv = 0.f;
#pragma unroll
        for (int ci = 0; ci < 4; ci++) {
            float wc = c_wt[j][ci];
            if (wc == 0.f) continue;
            rowv = fmaf(wc, src[r * 26 + cc0 + ci], rowv);
        }
        acc = fmaf(wr, rowv, acc);
    }
    g_pool[(size_t)bc * NP + n] = acc;
}

// ============================================================
// F / G projections: grid (2, BATCH)
// ============================================================
__global__ __launch_bounds__(256, 2) void fg_kernel(
    const float* __restrict__ x,
    const float* __restrict__ f_w, const float* __restrict__ f_b,
    const float* __restrict__ g_w, const float* __restrict__ g_b)
{
    __shared__ Buf bufs[2];
    int b   = blockIdx.y;
    int tid = threadIdx.x;
    int tx  = tid & 15, ty = tid >> 4;

    const float* W    = blockIdx.x ? g_w : f_w;
    const float* bias = blockIdx.x ? g_b : f_b;
    float* Out = (blockIdx.x ? g_G : g_F) + (size_t)b * 64 * NP;
    const float* In = x + (size_t)b * 512 * NTOK;

    ull acc[4][6] = {};
    run_gemm<0>(bufs, acc, W, 0, 64, In, NTOK, 512, tid, tx, ty);

#pragma unroll
    for (int r = 0; r < 4; r++) {
        int m = ty * 4 + r;
        float bv = bias[m];
        float* orow = Out + (size_t)m * NP;
#pragma unroll
        for (int jp = 0; jp < 6; jp++) {
            int col = 2 * tx + 32 * jp;
            if (col + 1 < NP) {
                float2 v = unpack2(acc[r][jp]);
                v.x += bv; v.y += bv;
                *(float2*)&orow[col] = v;
            }
        }
    }
}

// ============================================================
// S = softmax(F^T G) + h_w@f8 + u_w@pool + (h_b+u_b)   grid (3, BATCH)
// ============================================================
__global__ __launch_bounds__(256, 2) void s_kernel(
    const float* __restrict__ f8,
    const float* __restrict__ h_w, const float* __restrict__ h_b,
    const float* __restrict__ u_w, const float* __restrict__ u_b)
{
    __shared__ Buf bufs[2];
    int b   = blockIdx.y;
    int n0  = blockIdx.x * 64;
    int tid = threadIdx.x;
    int tx  = tid & 15, ty = tid >> 4;

    const float* Fb = g_F + (size_t)b * 64 * NP;
    const float* Gb = g_G + (size_t)b * 64 * NP;

    ull acc[4][6] = {};

    // energy = F^T G  (K = 64)
    run_gemm<1>(bufs, acc, Fb, n0, 0, Gb, NP, 64, tid, tx, ty);

    // softmax in place over cols (16 lanes per row, shfl width 16)
#pragma unroll
    for (int r = 0; r < 4; r++) {
        float v[12];
#pragma unroll
        for (int jp = 0; jp < 6; jp++) {
            float2 f = unpack2(acc[r][jp]);
            v[2 * jp] = f.x; v[2 * jp + 1] = f.y;
        }
        float mx = -CUDART_INF_F;
#pragma unroll
        for (int j = 0; j < 12; j++) {
            int col = 2 * tx + 32 * (j >> 1) + (j & 1);
            if (col < NTOK) mx = fmaxf(mx, v[j]);
        }
#pragma unroll
        for (int off = 8; off > 0; off >>= 1)
            mx = fmaxf(mx, __shfl_xor_sync(0xffffffffu, mx, off, 16));
        float sum = 0.f;
#pragma unroll
        for (int j = 0; j < 12; j++) {
            int col = 2 * tx + 32 * (j >> 1) + (j & 1);
            float e = (col < NTOK) ? __expf(v[j] - mx) : 0.f;
            v[j] = e; sum += e;
        }
#pragma unroll
        for (int off = 8; off > 0; off >>= 1)
            sum += __shfl_xor_sync(0xffffffffu, sum, off, 16);
        float inv = 1.f / sum;
#pragma unroll
        for (int jp = 0; jp < 6; jp++)
            acc[r][jp] = pack2(v[2 * jp] * inv, v[2 * jp + 1] * inv);
    }

    // += h_w @ f8   (K = 256)
    const float* f8b = f8 + (size_t)b * 256 * NTOK;
    run_gemm<0>(bufs, acc, h_w, n0, NTOK, f8b, NTOK, 256, tid, tx, ty);
    // += u_w @ pool (K = 128)
    const float* plb = g_pool + (size_t)b * 128 * NP;
    run_gemm<0>(bufs, acc, u_w, n0, NTOK, plb, NP, 128, tid, tx, ty);

    // write S (padded)
    float* Sb = g_S + (size_t)b * NTOK * NP;
#pragma unroll
    for (int r = 0; r < 4; r++) {
        int n = n0 + ty * 4 + r;
        if (n >= NTOK) continue;
        float bv = h_b[n] + u_b[n];
        float* srow = Sb + (size_t)n * NP;
#pragma unroll
        for (int jp = 0; jp < 6; jp++) {
            int col = 2 * tx + 32 * jp;
            if (col + 1 < NP) {
                float2 v = unpack2(acc[r][jp]);
                v.x += bv; v.y += bv;
                *(float2*)&srow[col] = v;
            }
        }
    }
}

// ============================================================
// out = gamma * (c_w @ S + c_b) + x     grid (8, BATCH)
// ============================================================
__global__ __launch_bounds__(256, 2) void out_kernel(
    const float* __restrict__ c_w, const float* __restrict__ c_b,
    const float* __restrict__ x, const float* __restrict__ gamma_p,
    float* __restrict__ Out)
{
    __shared__ Buf bufs[2];
    int b   = blockIdx.y;
    int m0  = blockIdx.x * 64;
    int tid = threadIdx.x;
    int tx  = tid & 15, ty = tid >> 4;

    const float* Sb = g_S + (size_t)b * NTOK * NP;

    ull acc[4][6] = {};
    run_gemm<0>(bufs, acc, c_w, m0, 512, Sb, NP, NTOK, tid, tx, ty);

    float gma = *gamma_p;
    const float* xb = x + (size_t)b * 512 * NTOK;
    float* ob = Out + (size_t)b * 512 * NTOK;
#pragma unroll
    for (int r = 0; r < 4; r++) {
        int m = m0 + ty * 4 + r;
        float bv = c_b[m];
        const float* xrow = xb + (size_t)m * NTOK;
        float* orow = ob + (size_t)m * NTOK;
#pragma unroll
        for (int jp = 0; jp < 6; jp++) {
            int col = 2 * tx + 32 * jp;
            float2 v = unpack2(acc[r][jp]);
            if (col     < NTOK) orow[col]     = fmaf(gma, v.x + bv, xrow[col]);
            if (col + 1 < NTOK) orow[col + 1] = fmaf(gma, v.y + bv, xrow[col + 1]);
        }
    }
}

// ============================================================
extern "C" void kernel_launch(void* const* d_in, const int* in_sizes, int n_in,
                              void* d_out, int out_size)
{
    const float* x    = (const float*)d_in[0];
    const float* f5   = (const float*)d_in[1];
    const float* f8   = (const float*)d_in[2];
    const float* f_w  = (const float*)d_in[3];
    const float* f_b  = (const float*)d_in[4];
    const float* g_w  = (const float*)d_in[5];
    const float* g_b  = (const float*)d_in[6];
    const float* h_w  = (const float*)d_in[7];
    const float* h_b  = (const float*)d_in[8];
    const float* u_w  = (const float*)d_in[9];
    const float* u_b  = (const float*)d_in[10];
    const float* c_w  = (const float*)d_in[11];
    const float* c_b  = (const float*)d_in[12];
    const float* gma  = (const float*)d_in[13];

    float* out = (float*)d_out;

    {
        int total = BATCH * 128 * NTOK;
        pool_kernel<<<(total + 255) / 256, 256>>>(f5);
    }
    fg_kernel<<<dim3(2, BATCH), 256>>>(x, f_w, f_b, g_w, g_b);
    s_kernel<<<dim3(3, BATCH), 256>>>(f8, h_w, h_b, u_w, u_b);
    out_kernel<<<dim3(8, BATCH), 256>>>(c_w, c_b, x, gma, out);
}